// round 2
// baseline (speedup 1.0000x reference)
#include <cuda_runtime.h>
#include <cstdint>
#include <math.h>

// Problem constants (fixed by the dataset)
#define BB 2
#define SS 2048
#define DD 512
#define HH 8
#define DH 64
#define BH (BB*HH)          // 16
#define MAXK 32
#define EPSF 1e-8f

// ---------------- scratch (static device globals; no allocs allowed) --------
__device__ float g_q  [BB*HH*SS*DH];   // [B,H,S,64]
__device__ float g_kT [BB*HH*DH*SS];   // [B,H,64,S]
__device__ float g_v  [BB*HH*SS*DH];   // [B,H,S,64]
__device__ float g_attn[BB*SS*DD];     // [B,S,D]

// ---------------- warp reduce helpers ---------------------------------------
__device__ __forceinline__ float warpMaxF(float v){
#pragma unroll
    for (int o = 16; o; o >>= 1) v = fmaxf(v, __shfl_xor_sync(0xffffffffu, v, o));
    return v;
}
__device__ __forceinline__ float warpSumF(float v){
#pragma unroll
    for (int o = 16; o; o >>= 1) v += __shfl_xor_sync(0xffffffffu, v, o);
    return v;
}
__device__ __forceinline__ unsigned warpMaxU(unsigned v){
#pragma unroll
    for (int o = 16; o; o >>= 1) { unsigned t = __shfl_xor_sync(0xffffffffu, v, o); v = t > v ? t : v; }
    return v;
}
__device__ __forceinline__ int warpSumI(int v){
#pragma unroll
    for (int o = 16; o; o >>= 1) v += __shfl_xor_sync(0xffffffffu, v, o);
    return v;
}
// monotone float -> uint mapping (descending float order == descending uint order)
__device__ __forceinline__ unsigned ordf(float f){
    unsigned u = __float_as_uint(f);
    return (u & 0x80000000u) ? ~u : (u | 0x80000000u);
}

// ---------------- SGEMM: C[M,N] = A[M,K] * Bw[N,K]^T + bias ------------------
// MODE 0: plain store to C.  MODE 1: scatter epilogue into g_q/g_kT/g_v.
template<int MODE>
__global__ __launch_bounds__(256)
void sgemm_nt(const float* __restrict__ A, const float* __restrict__ Bw,
              const float* __restrict__ bias, float* __restrict__ C,
              int M, int N, int K)
{
    const int BM = 128, BN = 128, BK = 16;
    __shared__ float As[BK][BM + 4];
    __shared__ float Bs[BK][BN + 4];

    int tid = threadIdx.x;
    int tx = tid & 15, ty = tid >> 4;
    int bm = blockIdx.y * BM, bn = blockIdx.x * BN;

    float acc[8][8];
#pragma unroll
    for (int i = 0; i < 8; i++)
#pragma unroll
        for (int j = 0; j < 8; j++) acc[i][j] = 0.f;

    const float* Ab = A + (size_t)bm * K;
    const float* Bb = Bw + (size_t)bn * K;

    for (int k0 = 0; k0 < K; k0 += BK) {
#pragma unroll
        for (int r = 0; r < 2; r++) {
            int f = tid + 256 * r;          // 0..511
            int row = f >> 2;
            int c4  = (f & 3) * 4;
            float4 av = *(const float4*)(Ab + (size_t)row * K + k0 + c4);
            As[c4 + 0][row] = av.x; As[c4 + 1][row] = av.y;
            As[c4 + 2][row] = av.z; As[c4 + 3][row] = av.w;
            float4 bv = *(const float4*)(Bb + (size_t)row * K + k0 + c4);
            Bs[c4 + 0][row] = bv.x; Bs[c4 + 1][row] = bv.y;
            Bs[c4 + 2][row] = bv.z; Bs[c4 + 3][row] = bv.w;
        }
        __syncthreads();
#pragma unroll
        for (int k = 0; k < BK; k++) {
            float4 a0 = *(const float4*)&As[k][ty * 8];
            float4 a1 = *(const float4*)&As[k][ty * 8 + 4];
            float4 b0 = *(const float4*)&Bs[k][tx * 8];
            float4 b1 = *(const float4*)&Bs[k][tx * 8 + 4];
            float av[8] = {a0.x,a0.y,a0.z,a0.w,a1.x,a1.y,a1.z,a1.w};
            float bv[8] = {b0.x,b0.y,b0.z,b0.w,b1.x,b1.y,b1.z,b1.w};
#pragma unroll
            for (int i = 0; i < 8; i++)
#pragma unroll
                for (int j = 0; j < 8; j++) acc[i][j] = fmaf(av[i], bv[j], acc[i][j]);
        }
        __syncthreads();
    }

    if (MODE == 0) {
#pragma unroll
        for (int i = 0; i < 8; i++) {
            int mrow = bm + ty * 8 + i;
#pragma unroll
            for (int g = 0; g < 2; g++) {
                int col = bn + tx * 8 + g * 4;
                float4 bv = *(const float4*)(bias + col);
                float4 o;
                o.x = acc[i][g*4+0] + bv.x; o.y = acc[i][g*4+1] + bv.y;
                o.z = acc[i][g*4+2] + bv.z; o.w = acc[i][g*4+3] + bv.w;
                *(float4*)(C + (size_t)mrow * N + col) = o;
            }
        }
    } else {
#pragma unroll
        for (int i = 0; i < 8; i++) {
            int mrow = bm + ty * 8 + i;
            int b = mrow >> 11;          // S = 2048
            int s = mrow & 2047;
#pragma unroll
            for (int j = 0; j < 8; j++) {
                int n = bn + tx * 8 + j;
                float val = acc[i][j] + bias[n];
                int sec = n >> 9;        // 0:q 1:k 2:v (D = 512)
                int nn  = n & 511;
                int head = nn >> 6, d = nn & 63;
                if (sec == 0)
                    g_q [((size_t)((b*HH+head)*SS) + s)*DH + d] = val;
                else if (sec == 1)
                    g_kT[((size_t)((b*HH+head)*DH) + d)*SS + s] = val;
                else
                    g_v [((size_t)((b*HH+head)*SS) + s)*DH + d] = val;
            }
        }
    }
}

// ---------------- fused attention: scores + softmax + entropy topk + sparse AV
// grid: (S/8, B*H), 256 threads. One warp owns one query row for phases 2-5.
#define TQ 8
#define CAP 256
#define ATTN_SMEM (TQ*SS*4 + DH*TQ*4 + TQ*4 + TQ*CAP*2)

__global__ __launch_bounds__(256, 2)
void attn_kernel()
{
    extern __shared__ unsigned char smem[];
    float* s_sc = (float*)smem;                               // [TQ][2048]
    float* s_qT = s_sc + TQ * SS;                             // [64][TQ]
    int*   s_cnt = (int*)(s_qT + DH * TQ);                    // [TQ]
    unsigned short* s_idx = (unsigned short*)(s_cnt + TQ);    // [TQ][CAP]

    int bh = blockIdx.y;
    int q0 = blockIdx.x * TQ;
    const float* Q  = g_q  + ((size_t)bh * SS + q0) * DH;
    const float* KT = g_kT + (size_t)bh * DH * SS;
    const float* V  = g_v  + (size_t)bh * SS * DH;
    int tid = threadIdx.x;

    // load Q tile transposed: s_qT[d][i]
    for (int e = tid; e < TQ * DH; e += 256) {
        int i = e >> 6, d = e & 63;
        s_qT[d * TQ + i] = Q[i * DH + d];
    }
    __syncthreads();

    int lane = tid & 31, w = tid >> 5;

    // ---- phase 1: scores, 8x8 micro-tile per thread over full K-dim --------
    int jA = w * 256 + lane * 4;
    int jB = jA + 128;
    float acc[8][8];
#pragma unroll
    for (int i = 0; i < 8; i++)
#pragma unroll
        for (int c = 0; c < 8; c++) acc[i][c] = 0.f;

#pragma unroll 16
    for (int d = 0; d < DH; d++) {
        const float* kr = KT + (size_t)d * SS;
        float4 ka = *(const float4*)(kr + jA);
        float4 kb = *(const float4*)(kr + jB);
        float4 qa = *(const float4*)(s_qT + d * TQ);
        float4 qb = *(const float4*)(s_qT + d * TQ + 4);
        float qq[8] = {qa.x,qa.y,qa.z,qa.w,qb.x,qb.y,qb.z,qb.w};
        float kk[8] = {ka.x,ka.y,ka.z,ka.w,kb.x,kb.y,kb.z,kb.w};
#pragma unroll
        for (int i = 0; i < 8; i++)
#pragma unroll
            for (int c = 0; c < 8; c++) acc[i][c] = fmaf(qq[i], kk[c], acc[i][c]);
    }
    const float scale = 0.125f;   // 1/sqrt(64)
#pragma unroll
    for (int i = 0; i < 8; i++) {
        float4 v0, v1;
        v0.x = acc[i][0]*scale; v0.y = acc[i][1]*scale; v0.z = acc[i][2]*scale; v0.w = acc[i][3]*scale;
        v1.x = acc[i][4]*scale; v1.y = acc[i][5]*scale; v1.z = acc[i][6]*scale; v1.w = acc[i][7]*scale;
        *(float4*)&s_sc[i * SS + jA] = v0;
        *(float4*)&s_sc[i * SS + jB] = v1;
    }
    __syncthreads();

    // ---- phase 2: per-row stats (warp w handles row w) ---------------------
    float* sc = s_sc + w * SS;

    float m = -3.0e38f;
#pragma unroll 8
    for (int jj = 0; jj < 64; jj++) m = fmaxf(m, sc[lane + (jj << 5)]);
    m = warpMaxF(m);

    float z = 0.f;
#pragma unroll 8
    for (int jj = 0; jj < 64; jj++) z += expf(sc[lane + (jj << 5)] - m);
    z = warpSumF(z);

    float invZ = 1.0f / z;
    float hent = 0.f;
#pragma unroll 8
    for (int jj = 0; jj < 64; jj++) {
        float p  = expf(sc[lane + (jj << 5)] - m);
        float ww = p * invZ;
        hent -= ww * logf(ww + EPSF);
    }
    hent = warpSumF(hent);

    int tk = (int)(32.0f * (1.0f - hent));   // trunc toward zero, like astype(int32)
    tk = tk < 1 ? 1 : (tk > MAXK ? MAXK : tk);

    // ---- phase 3: exact k-th largest (tie-aware, ordered-uint space) -------
    unsigned thr_u;
    if (tk == 1) {
        thr_u = ordf(m);
    } else {
        thr_u = 0xFFFFFFFFu;
        int removed = 0;
        while (removed < tk) {
            unsigned best = 0u;
            for (int jj = 0; jj < 64; jj++) {
                unsigned u = ordf(sc[lane + (jj << 5)]);
                if (u < thr_u && u > best) best = u;
            }
            best = warpMaxU(best);
            int c = 0;
            for (int jj = 0; jj < 64; jj++)
                c += (ordf(sc[lane + (jj << 5)]) == best);
            c = warpSumI(c);
            removed += c;
            thr_u = best;
        }
    }

    // ---- phase 4: compact kept indices + P sum -----------------------------
    if (lane == 0) s_cnt[w] = 0;
    __syncwarp();
    float P = 0.f;
    for (int jj = 0; jj < 64; jj++) {
        int j = lane + (jj << 5);
        float s = sc[j];
        if (ordf(s) >= thr_u) {
            P += expf(s - m);
            int pos = atomicAdd(&s_cnt[w], 1);
            if (pos < CAP) s_idx[w * CAP + pos] = (unsigned short)j;
        }
    }
    P = warpSumF(P);
    __syncwarp();
    int cnt = s_cnt[w];
    float invDen = 1.0f / (P + EPSF * z);   // p/(P + EPS*Z) == (p/Z)/(P/Z + EPS)

    // ---- phase 5: sparse p*V accumulate (lane owns dims 2*lane, 2*lane+1) --
    int d0 = lane * 2;
    float a0 = 0.f, a1 = 0.f;
    if (cnt <= CAP) {
        for (int t = 0; t < cnt; t++) {
            int j = s_idx[w * CAP + t];
            float p = expf(sc[j] - m);
            float2 vv = *(const float2*)(V + (size_t)j * DH + d0);
            a0 = fmaf(p, vv.x, a0);
            a1 = fmaf(p, vv.y, a1);
        }
    } else {  // pathological tie overflow fallback
        for (int j = 0; j < SS; j++) {
            float s = sc[j];
            if (ordf(s) >= thr_u) {
                float p = expf(s - m);
                float2 vv = *(const float2*)(V + (size_t)j * DH + d0);
                a0 = fmaf(p, vv.x, a0);
                a1 = fmaf(p, vv.y, a1);
            }
        }
    }
    a0 *= invDen; a1 *= invDen;

    int b = bh >> 3, hd = bh & 7;
    int srow = q0 + w;
    float2 o; o.x = a0; o.y = a1;
    *(float2*)&g_attn[((size_t)(b * SS + srow)) * DD + hd * DH + d0] = o;
}

// ---------------- launch -----------------------------------------------------
extern "C" void kernel_launch(void* const* d_in, const int* in_sizes, int n_in,
                              void* d_out, int out_size)
{
    const float* x     = (const float*)d_in[0];
    const float* w_in  = (const float*)d_in[1];
    const float* b_in  = (const float*)d_in[2];
    const float* w_out = (const float*)d_in[3];
    const float* b_out = (const float*)d_in[4];
    float* out = (float*)d_out;

    float* pattn = nullptr;
    cudaGetSymbolAddress((void**)&pattn, g_attn);

    cudaFuncSetAttribute(attn_kernel,
                         cudaFuncAttributeMaxDynamicSharedMemorySize, ATTN_SMEM);

    // 1) QKV projection with head-layout scatter
    sgemm_nt<1><<<dim3((3*DD)/128, (BB*SS)/128), 256>>>(
        x, w_in, b_in, nullptr, BB*SS, 3*DD, DD);

    // 2) fused attention + entropy top-k + sparse AV
    attn_kernel<<<dim3(SS/TQ, BH), 256, ATTN_SMEM>>>();

    // 3) output projection
    sgemm_nt<0><<<dim3(DD/128, (BB*SS)/128), 256>>>(
        pattn, w_out, b_out, out, BB*SS, DD, DD);
}

// round 3
// speedup vs baseline: 1.1575x; 1.1575x over previous
#include <cuda_runtime.h>
#include <cstdint>
#include <math.h>

// Problem constants (fixed by the dataset)
#define BB 2
#define SS 2048
#define DD 512
#define HH 8
#define DH 64
#define BH (BB*HH)          // 16
#define MAXK 32
#define EPSF 1e-8f

// ---------------- scratch (static device globals; no allocs allowed) --------
__device__ float g_q  [BB*HH*SS*DH];   // [B,H,S,64]
__device__ float g_kT [BB*HH*DH*SS];   // [B,H,64,S]
__device__ float g_v  [BB*HH*SS*DH];   // [B,H,S,64]
__device__ float g_attn[BB*SS*DD];     // [B,S,D]

// ---------------- warp reduce helpers ---------------------------------------
__device__ __forceinline__ float warpMaxF(float v){
#pragma unroll
    for (int o = 16; o; o >>= 1) v = fmaxf(v, __shfl_xor_sync(0xffffffffu, v, o));
    return v;
}
__device__ __forceinline__ float warpSumF(float v){
#pragma unroll
    for (int o = 16; o; o >>= 1) v += __shfl_xor_sync(0xffffffffu, v, o);
    return v;
}
__device__ __forceinline__ unsigned warpMaxU(unsigned v){
#pragma unroll
    for (int o = 16; o; o >>= 1) { unsigned t = __shfl_xor_sync(0xffffffffu, v, o); v = t > v ? t : v; }
    return v;
}
__device__ __forceinline__ int warpSumI(int v){
#pragma unroll
    for (int o = 16; o; o >>= 1) v += __shfl_xor_sync(0xffffffffu, v, o);
    return v;
}
// monotone float -> uint mapping (descending float order == descending uint order)
__device__ __forceinline__ unsigned ordf(float f){
    unsigned u = __float_as_uint(f);
    return (u & 0x80000000u) ? ~u : (u | 0x80000000u);
}

// ---------------- SGEMM: C[M,N] = A[M,K] * Bw[N,K]^T + bias ------------------
// Double-buffered smem pipeline. MODE 0: plain store. MODE 1: q/kT/v scatter.
template<int MODE>
__global__ __launch_bounds__(256, 2)
void sgemm_nt(const float* __restrict__ A, const float* __restrict__ Bw,
              const float* __restrict__ bias, float* __restrict__ C,
              int M, int N, int K)
{
    const int BM = 128, BN = 128, BK = 16;
    __shared__ float As[2][BK][BM + 4];
    __shared__ float Bs[2][BK][BN + 4];

    int tid = threadIdx.x;
    int tx = tid & 15, ty = tid >> 4;
    int bm = blockIdx.y * BM, bn = blockIdx.x * BN;

    // loader mapping: f = tid + 256*r (r=0,1), row = f>>2, c4 = (f&3)*4
    int lrow0 = tid >> 2,            lc0 = (tid & 3) * 4;
    int lrow1 = (tid + 256) >> 2,    lc1 = lc0;   // same (f&3) pattern

    float acc[8][8];
#pragma unroll
    for (int i = 0; i < 8; i++)
#pragma unroll
        for (int j = 0; j < 8; j++) acc[i][j] = 0.f;

    const float* Ab = A + (size_t)bm * K;
    const float* Bb = Bw + (size_t)bn * K;

    float4 pa0, pa1, pb0, pb1;

    // prologue: load k0 = 0 tile
    pa0 = *(const float4*)(Ab + (size_t)lrow0 * K + lc0);
    pa1 = *(const float4*)(Ab + (size_t)lrow1 * K + lc1);
    pb0 = *(const float4*)(Bb + (size_t)lrow0 * K + lc0);
    pb1 = *(const float4*)(Bb + (size_t)lrow1 * K + lc1);
    As[0][lc0 + 0][lrow0] = pa0.x; As[0][lc0 + 1][lrow0] = pa0.y;
    As[0][lc0 + 2][lrow0] = pa0.z; As[0][lc0 + 3][lrow0] = pa0.w;
    As[0][lc1 + 0][lrow1] = pa1.x; As[0][lc1 + 1][lrow1] = pa1.y;
    As[0][lc1 + 2][lrow1] = pa1.z; As[0][lc1 + 3][lrow1] = pa1.w;
    Bs[0][lc0 + 0][lrow0] = pb0.x; Bs[0][lc0 + 1][lrow0] = pb0.y;
    Bs[0][lc0 + 2][lrow0] = pb0.z; Bs[0][lc0 + 3][lrow0] = pb0.w;
    Bs[0][lc1 + 0][lrow1] = pb1.x; Bs[0][lc1 + 1][lrow1] = pb1.y;
    Bs[0][lc1 + 2][lrow1] = pb1.z; Bs[0][lc1 + 3][lrow1] = pb1.w;
    __syncthreads();

    for (int k0 = 0; k0 < K; k0 += BK) {
        int buf = (k0 >> 4) & 1;
        bool more = (k0 + BK) < K;
        // issue next-tile global loads early (latency hidden by compute)
        if (more) {
            int kn = k0 + BK;
            pa0 = *(const float4*)(Ab + (size_t)lrow0 * K + kn + lc0);
            pa1 = *(const float4*)(Ab + (size_t)lrow1 * K + kn + lc1);
            pb0 = *(const float4*)(Bb + (size_t)lrow0 * K + kn + lc0);
            pb1 = *(const float4*)(Bb + (size_t)lrow1 * K + kn + lc1);
        }
#pragma unroll
        for (int k = 0; k < BK; k++) {
            float4 a0 = *(const float4*)&As[buf][k][ty * 8];
            float4 a1 = *(const float4*)&As[buf][k][ty * 8 + 4];
            float4 b0 = *(const float4*)&Bs[buf][k][tx * 8];
            float4 b1 = *(const float4*)&Bs[buf][k][tx * 8 + 4];
            float av[8] = {a0.x,a0.y,a0.z,a0.w,a1.x,a1.y,a1.z,a1.w};
            float bv[8] = {b0.x,b0.y,b0.z,b0.w,b1.x,b1.y,b1.z,b1.w};
#pragma unroll
            for (int i = 0; i < 8; i++)
#pragma unroll
                for (int j = 0; j < 8; j++) acc[i][j] = fmaf(av[i], bv[j], acc[i][j]);
        }
        if (more) {
            int nb = buf ^ 1;
            As[nb][lc0 + 0][lrow0] = pa0.x; As[nb][lc0 + 1][lrow0] = pa0.y;
            As[nb][lc0 + 2][lrow0] = pa0.z; As[nb][lc0 + 3][lrow0] = pa0.w;
            As[nb][lc1 + 0][lrow1] = pa1.x; As[nb][lc1 + 1][lrow1] = pa1.y;
            As[nb][lc1 + 2][lrow1] = pa1.z; As[nb][lc1 + 3][lrow1] = pa1.w;
            Bs[nb][lc0 + 0][lrow0] = pb0.x; Bs[nb][lc0 + 1][lrow0] = pb0.y;
            Bs[nb][lc0 + 2][lrow0] = pb0.z; Bs[nb][lc0 + 3][lrow0] = pb0.w;
            Bs[nb][lc1 + 0][lrow1] = pb1.x; Bs[nb][lc1 + 1][lrow1] = pb1.y;
            Bs[nb][lc1 + 2][lrow1] = pb1.z; Bs[nb][lc1 + 3][lrow1] = pb1.w;
        }
        __syncthreads();
    }

    if (MODE == 0) {
#pragma unroll
        for (int i = 0; i < 8; i++) {
            int mrow = bm + ty * 8 + i;
#pragma unroll
            for (int g = 0; g < 2; g++) {
                int col = bn + tx * 8 + g * 4;
                float4 bv = *(const float4*)(bias + col);
                float4 o;
                o.x = acc[i][g*4+0] + bv.x; o.y = acc[i][g*4+1] + bv.y;
                o.z = acc[i][g*4+2] + bv.z; o.w = acc[i][g*4+3] + bv.w;
                *(float4*)(C + (size_t)mrow * N + col) = o;
            }
        }
    } else {
#pragma unroll
        for (int i = 0; i < 8; i++) {
            int mrow = bm + ty * 8 + i;
            int b = mrow >> 11;          // S = 2048
            int s = mrow & 2047;
#pragma unroll
            for (int j = 0; j < 8; j++) {
                int n = bn + tx * 8 + j;
                float val = acc[i][j] + bias[n];
                int sec = n >> 9;        // 0:q 1:k 2:v (D = 512)
                int nn  = n & 511;
                int head = nn >> 6, d = nn & 63;
                if (sec == 0)
                    g_q [((size_t)((b*HH+head)*SS) + s)*DH + d] = val;
                else if (sec == 1)
                    g_kT[((size_t)((b*HH+head)*DH) + d)*SS + s] = val;
                else
                    g_v [((size_t)((b*HH+head)*SS) + s)*DH + d] = val;
            }
        }
    }
}

// ---------------- fused attention v2 -----------------------------------------
// TQ=16 queries/block, 512 threads (16 warps). Phase 1: each warp computes a
// 16x128 score slab (thread tile 16x4), fused per-row max. Phase 2: warp w owns
// row w; single exp pass accumulates Z and S1=sum p*(s-m) -> entropy identity
// H = logZ - S1/Z, and records argmax ties. Fast path (H>=1.2 => tk=1): output
// = sum of tied V rows / (cnt + EPS*Z). Exact fallback otherwise (scores are
// still in smem).
#define TQ 16
#define ATHREADS 512
#define CAP 128
#define ATTN_SMEM (TQ*SS*4 + DH*TQ*4 + TQ*16*4 + TQ*4 + TQ*CAP*2)

__global__ __launch_bounds__(ATHREADS, 1)
void attn_kernel()
{
    extern __shared__ unsigned char smem[];
    float* s_sc  = (float*)smem;                              // [TQ][2048]
    float* s_qT  = s_sc + TQ * SS;                            // [64][TQ]
    float* s_max = s_qT + DH * TQ;                            // [TQ][16]
    int*   s_cnt = (int*)(s_max + TQ * 16);                   // [TQ]
    unsigned short* s_idx = (unsigned short*)(s_cnt + TQ);    // [TQ][CAP]

    int bh = blockIdx.y;
    int q0 = blockIdx.x * TQ;
    const float* Q  = g_q  + ((size_t)bh * SS + q0) * DH;
    const float* KT = g_kT + (size_t)bh * DH * SS;
    const float* V  = g_v  + (size_t)bh * SS * DH;
    int tid = threadIdx.x;
    int lane = tid & 31, w = tid >> 5;

    // load Q tile transposed: s_qT[d][i]
    for (int e = tid; e < TQ * DH; e += ATHREADS) {
        int i = e & 15, d = e >> 4;
        s_qT[d * TQ + i] = Q[i * DH + d];
    }
    __syncthreads();

    // ---- phase 1: scores. warp w covers cols [128w, 128w+128), 16 rows -----
    int c0 = w * 128 + lane * 4;
    float acc[16][4];
#pragma unroll
    for (int i = 0; i < 16; i++)
#pragma unroll
        for (int c = 0; c < 4; c++) acc[i][c] = 0.f;

#pragma unroll 4
    for (int d = 0; d < DH; d++) {
        float4 k4 = *(const float4*)(KT + (size_t)d * SS + c0);
        const float4* qp = (const float4*)(s_qT + d * TQ);
        float4 q4[4] = {qp[0], qp[1], qp[2], qp[3]};
        const float* qf = (const float*)q4;
#pragma unroll
        for (int i = 0; i < 16; i++) {
            float qi = qf[i];
            acc[i][0] = fmaf(qi, k4.x, acc[i][0]);
            acc[i][1] = fmaf(qi, k4.y, acc[i][1]);
            acc[i][2] = fmaf(qi, k4.z, acc[i][2]);
            acc[i][3] = fmaf(qi, k4.w, acc[i][3]);
        }
    }
    const float scale = 0.125f;   // 1/sqrt(64)
#pragma unroll
    for (int i = 0; i < 16; i++) {
        float4 v;
        v.x = acc[i][0]*scale; v.y = acc[i][1]*scale;
        v.z = acc[i][2]*scale; v.w = acc[i][3]*scale;
        *(float4*)&s_sc[i * SS + c0] = v;
        float rm = fmaxf(fmaxf(v.x, v.y), fmaxf(v.z, v.w));
        rm = warpMaxF(rm);
        if (lane == 0) s_max[i * 16 + w] = rm;      // per-warp partial row max
    }
    if (lane == 0) s_cnt[w] = 0;
    __syncthreads();

    // ---- phase 2: warp w owns row w ----------------------------------------
    float* sc = s_sc + w * SS;
    float m;
    {
        float t = (lane < 16) ? s_max[w * 16 + lane] : -3.0e38f;
        m = warpMaxF(t);
    }

    // single pass: Z, S1 = sum p*(s-m), argmax-tie recording
    float z = 0.f, s1 = 0.f;
#pragma unroll 4
    for (int jj = 0; jj < 64; jj++) {
        int j = lane + (jj << 5);
        float s = sc[j];
        float x = s - m;
        float p = expf(x);
        z += p;
        s1 = fmaf(p, x, s1);
        if (s >= m) {   // tie with max (s <= m always)
            int pos = atomicAdd(&s_cnt[w], 1);
            if (pos < CAP) s_idx[w * CAP + pos] = (unsigned short)j;
        }
    }
    z  = warpSumF(z);
    s1 = warpSumF(s1);
    float hent = logf(z) - s1 / z;   // == -sum w log w (eps-free identity)
    __syncwarp();
    int cnt = s_cnt[w];

    int b = bh >> 3, hd = bh & 7;
    float* outp = &g_attn[((size_t)(b * SS + q0 + w)) * DD + hd * DH + lane * 2];

    if (hent >= 1.2f && cnt <= CAP) {
        // tk = 1 guaranteed (32*(1-H) < 1). kept set = argmax ties, p = 1 each.
        float wgt = 1.0f / ((float)cnt + EPSF * z);
        int d0 = lane * 2;
        float a0 = 0.f, a1 = 0.f;
        for (int t = 0; t < cnt; t++) {
            int j = s_idx[w * CAP + t];
            float2 vv = *(const float2*)(V + (size_t)j * DH + d0);
            a0 += vv.x; a1 += vv.y;
        }
        float2 o; o.x = a0 * wgt; o.y = a1 * wgt;
        *(float2*)outp = o;
    } else {
        // ---- exact general path (rare): reference-style entropy + topk ----
        float invZ = 1.0f / z;
        float he = 0.f;
        for (int jj = 0; jj < 64; jj++) {
            float p  = expf(sc[lane + (jj << 5)] - m);
            float ww = p * invZ;
            he -= ww * logf(ww + EPSF);
        }
        he = warpSumF(he);
        int tk = (int)(32.0f * (1.0f - he));
        tk = tk < 1 ? 1 : (tk > MAXK ? MAXK : tk);

        unsigned thr_u;
        if (tk == 1) {
            thr_u = ordf(m);
        } else {
            thr_u = 0xFFFFFFFFu;
            int removed = 0;
            while (removed < tk) {
                unsigned best = 0u;
                for (int jj = 0; jj < 64; jj++) {
                    unsigned u = ordf(sc[lane + (jj << 5)]);
                    if (u < thr_u && u > best) best = u;
                }
                best = warpMaxU(best);
                int c = 0;
                for (int jj = 0; jj < 64; jj++)
                    c += (ordf(sc[lane + (jj << 5)]) == best);
                c = warpSumI(c);
                removed += c;
                thr_u = best;
            }
        }

        if (lane == 0) s_cnt[w] = 0;
        __syncwarp();
        float P = 0.f;
        for (int jj = 0; jj < 64; jj++) {
            int j = lane + (jj << 5);
            float s = sc[j];
            if (ordf(s) >= thr_u) {
                P += expf(s - m);
                int pos = atomicAdd(&s_cnt[w], 1);
                if (pos < CAP) s_idx[w * CAP + pos] = (unsigned short)j;
            }
        }
        P = warpSumF(P);
        __syncwarp();
        int gcnt = s_cnt[w];
        float invDen = 1.0f / (P + EPSF * z);

        int d0 = lane * 2;
        float a0 = 0.f, a1 = 0.f;
        if (gcnt <= CAP) {
            for (int t = 0; t < gcnt; t++) {
                int j = s_idx[w * CAP + t];
                float p = expf(sc[j] - m);
                float2 vv = *(const float2*)(V + (size_t)j * DH + d0);
                a0 = fmaf(p, vv.x, a0);
                a1 = fmaf(p, vv.y, a1);
            }
        } else {
            for (int j = 0; j < SS; j++) {
                float s = sc[j];
                if (ordf(s) >= thr_u) {
                    float p = expf(s - m);
                    float2 vv = *(const float2*)(V + (size_t)j * DH + d0);
                    a0 = fmaf(p, vv.x, a0);
                    a1 = fmaf(p, vv.y, a1);
                }
            }
        }
        float2 o; o.x = a0 * invDen; o.y = a1 * invDen;
        *(float2*)outp = o;
    }
}

// ---------------- launch -----------------------------------------------------
extern "C" void kernel_launch(void* const* d_in, const int* in_sizes, int n_in,
                              void* d_out, int out_size)
{
    const float* x     = (const float*)d_in[0];
    const float* w_in  = (const float*)d_in[1];
    const float* b_in  = (const float*)d_in[2];
    const float* w_out = (const float*)d_in[3];
    const float* b_out = (const float*)d_in[4];
    float* out = (float*)d_out;

    float* pattn = nullptr;
    cudaGetSymbolAddress((void**)&pattn, g_attn);

    cudaFuncSetAttribute(attn_kernel,
                         cudaFuncAttributeMaxDynamicSharedMemorySize, ATTN_SMEM);

    // 1) QKV projection with head-layout scatter
    sgemm_nt<1><<<dim3((3*DD)/128, (BB*SS)/128), 256>>>(
        x, w_in, b_in, nullptr, BB*SS, 3*DD, DD);

    // 2) fused attention + entropy top-k + sparse AV
    attn_kernel<<<dim3(SS/TQ, BH), ATHREADS, ATTN_SMEM>>>();

    // 3) output projection
    sgemm_nt<0><<<dim3(DD/128, (BB*SS)/128), 256>>>(
        pattn, w_out, b_out, out, BB*SS, DD, DD);
}